// round 5
// baseline (speedup 1.0000x reference)
#include <cuda_runtime.h>
#include <math.h>

// ---------------- problem dims ----------------
#define T_  64
#define B_  512
#define E_  1536
#define A_  7
#define D_  2048
#define S_  32
#define H_  1024
#define DS_ 2080      // D + S
#define G3_ 6144      // 3*D
#define P2_ 64        // 2*S

// ---------------- device scratch (no allocs allowed) ----------------
__device__ __align__(16) float g_state[B_ * DS_];
__device__ __align__(16) float g_za[B_ * H_];
__device__ __align__(16) float g_gi[B_ * G3_];
__device__ __align__(16) float g_gh[B_ * G3_];
__device__ __align__(16) float g_x12[B_ * 2 * H_];
__device__ __align__(16) float g_epost[(size_t)T_ * B_ * H_];   // 134 MB
__device__ __align__(16) float g_Wcat[D_ * 2 * H_];             // [2048, 2048]
__device__ __align__(16) float g_bcat[2 * H_];
__device__ int g_reset_mode;   // 0 = bool(1B), 1 = int32, 2 = float32

// ---------------- helpers ----------------
__device__ __forceinline__ float elu_f(float x) { return x > 0.f ? x : expm1f(x); }
__device__ __forceinline__ float sigmoid_f(float x) { return 1.f / (1.f + expf(-x)); }
__device__ __forceinline__ float softplus_f(float x) {
    return fmaxf(x, 0.f) + log1pf(expf(-fabsf(x)));
}

// ---------------- reset dtype sniffer ----------------
// Inspect first T_*B_ bytes (minimum possible buffer size for any layout).
// bool(1B):  ~50% of ALL byte positions nonzero -> nonzero seen at i%4!=0.
// int32 0/1: only bytes at i%4==0 can be nonzero (little-endian), none at i%4!=0.
// float32 1.0f: byte at i%4==3 is 0x3F wherever value==1.0.
__global__ void detect_reset_kernel(const unsigned char* __restrict__ rbytes) {
    __shared__ int sawOdd, sawF32;
    if (threadIdx.x == 0) { sawOdd = 0; sawF32 = 0; }
    __syncthreads();
    for (int i = threadIdx.x; i < T_ * B_; i += blockDim.x) {
        unsigned char v = rbytes[i];
        if ((i & 3) == 3 && v == 0x3F) sawF32 = 1;
        if ((i & 3) != 0 && v != 0)    sawOdd = 1;
    }
    __syncthreads();
    if (threadIdx.x == 0) {
        g_reset_mode = sawF32 ? 2 : (sawOdd ? 0 : 1);
    }
}

__device__ __forceinline__ bool read_reset(const void* rp, int idx) {
    int mode = g_reset_mode;
    if (mode == 0) return ((const unsigned char*)rp)[idx] != 0;
    if (mode == 1) return ((const int*)rp)[idx] != 0;
    return ((const float*)rp)[idx] != 0.f;
}

// ---------------- generic fp32 tiled GEMM ----------------
template<int BM, int BN, int BK, int TM, int TN>
__global__ void __launch_bounds__(256) gemm_f32(
    int M, int N, int K,
    const float* __restrict__ A, int lda,
    const float* __restrict__ B, int ldb,
    float* __restrict__ C, int ldc,
    const float* __restrict__ bias,
    const float* __restrict__ add, int addStart, int addLd,
    int doElu)
{
    __shared__ __align__(16) float As[BK][BM];
    __shared__ __align__(16) float Bs[BK][BN];

    const int tid = threadIdx.x;
    const int m0 = blockIdx.y * BM;
    const int n0 = blockIdx.x * BN;

    constexpr int AKV = BK / 4;
    const int aRow = tid / AKV;
    const int aCol = (tid % AKV) * 4;
    constexpr int BNV = BN / 4;
    const int bRow = tid / BNV;
    const int bCol = (tid % BNV) * 4;

    constexpr int TC = BN / TN;
    const int tr = tid / TC;
    const int tc = tid % TC;

    float acc[TM][TN];
#pragma unroll
    for (int i = 0; i < TM; i++)
#pragma unroll
        for (int j = 0; j < TN; j++) acc[i][j] = 0.f;

    for (int k0 = 0; k0 < K; k0 += BK) {
        float4 av = *reinterpret_cast<const float4*>(&A[(size_t)(m0 + aRow) * lda + k0 + aCol]);
        As[aCol + 0][aRow] = av.x;
        As[aCol + 1][aRow] = av.y;
        As[aCol + 2][aRow] = av.z;
        As[aCol + 3][aRow] = av.w;
        float4 bv = *reinterpret_cast<const float4*>(&B[(size_t)(k0 + bRow) * ldb + n0 + bCol]);
        *reinterpret_cast<float4*>(&Bs[bRow][bCol]) = bv;
        __syncthreads();

#pragma unroll
        for (int k = 0; k < BK; k++) {
            float ra[TM], rb[TN];
#pragma unroll
            for (int i = 0; i < TM; i++) ra[i] = As[k][tr * TM + i];
#pragma unroll
            for (int j = 0; j < TN; j++) rb[j] = Bs[k][tc * TN + j];
#pragma unroll
            for (int i = 0; i < TM; i++)
#pragma unroll
                for (int j = 0; j < TN; j++) acc[i][j] = fmaf(ra[i], rb[j], acc[i][j]);
        }
        __syncthreads();
    }

#pragma unroll
    for (int i = 0; i < TM; i++) {
        const int r = m0 + tr * TM + i;
#pragma unroll
        for (int j = 0; j < TN; j++) {
            const int c = n0 + tc * TN + j;
            float v = acc[i][j];
            if (bias) v += bias[c];
            if (add && c >= addStart) v += add[(size_t)r * addLd + (c - addStart)];
            if (doElu) v = elu_f(v);
            C[(size_t)r * ldc + c] = v;
        }
    }
}

// ---------------- small kernels ----------------
__global__ void copy_state_kernel(const float* __restrict__ in_state, float* __restrict__ state) {
    int idx = blockIdx.x * blockDim.x + threadIdx.x;
    if (idx < B_ * DS_) state[idx] = in_state[idx];
}

// Zero state rows where reset[t*B + b] is true (element index computed in-kernel
// because element width depends on the detected dtype).
__global__ void reset_kernel(const void* __restrict__ reset_base, int t, float* __restrict__ state) {
    int idx = blockIdx.x * blockDim.x + threadIdx.x;
    if (idx >= B_ * DS_) return;
    int b = idx / DS_;
    if (read_reset(reset_base, t * B_ + b)) state[idx] = 0.f;
}

__global__ void wcat_kernel(const float* __restrict__ pW1, const float* __restrict__ pb1,
                            const float* __restrict__ qW1, const float* __restrict__ qb1,
                            float* __restrict__ Wcat, float* __restrict__ bcat) {
    int idx = blockIdx.x * blockDim.x + threadIdx.x;
    if (idx < D_ * 2 * H_) {
        int k = idx / (2 * H_);
        int j = idx % (2 * H_);
        Wcat[idx] = (j < H_) ? pW1[k * H_ + j] : qW1[k * H_ + (j - H_)];
    }
    if (idx < 2 * H_) bcat[idx] = (idx < H_) ? pb1[idx] : qb1[idx - H_];
}

// za = elu(concat(z, a) @ za_W + za_b)
__global__ void za_kernel(const float* __restrict__ state, const float* __restrict__ action_t,
                          const float* __restrict__ za_W, const float* __restrict__ za_b,
                          float* __restrict__ za) {
    int idx = blockIdx.x * blockDim.x + threadIdx.x;
    if (idx >= B_ * H_) return;
    int b = idx / H_;
    int j = idx % H_;
    float acc = za_b[j];
    const float* z = state + (size_t)b * DS_ + D_;
#pragma unroll
    for (int k = 0; k < S_; k++) acc = fmaf(z[k], za_W[k * H_ + j], acc);
    const float* a = action_t + (size_t)b * A_;
#pragma unroll
    for (int k = 0; k < A_; k++) acc = fmaf(a[k], za_W[(S_ + k) * H_ + j], acc);
    za[idx] = elu_f(acc);
}

// GRU gate combine
__global__ void gate_kernel(const float* __restrict__ gi, const float* __restrict__ gh,
                            float* __restrict__ state, float* __restrict__ out_states_t) {
    int idx = blockIdx.x * blockDim.x + threadIdx.x;
    if (idx >= B_ * D_) return;
    int b = idx / D_;
    int i = idx % D_;
    const float* gib = gi + (size_t)b * G3_;
    const float* ghb = gh + (size_t)b * G3_;
    float ir = gib[i], iz = gib[D_ + i], inn = gib[2 * D_ + i];
    float hr = ghb[i], hz = ghb[D_ + i], hn = ghb[2 * D_ + i];
    float h = state[(size_t)b * DS_ + i];
    float rg = sigmoid_f(ir + hr);
    float zg = sigmoid_f(iz + hz);
    float n = tanhf(inn + rg * hn);
    float hnew = (1.f - zg) * n + zg * h;
    state[(size_t)b * DS_ + i] = hnew;
    out_states_t[(size_t)b * DS_ + i] = hnew;
}

// Heads: prior/post W2 matmuls + mean/std + sample
__global__ void heads_kernel(const float* __restrict__ x12,
                             const float* __restrict__ prior_W2, const float* __restrict__ prior_b2,
                             const float* __restrict__ post_W2, const float* __restrict__ post_b2,
                             const float* __restrict__ noise_t,
                             float* __restrict__ state,
                             float* __restrict__ out_priors_t, float* __restrict__ out_posts_t,
                             float* __restrict__ out_states_t) {
    int gid = blockIdx.x * blockDim.x + threadIdx.x;
    if (gid >= B_ * 64) return;
    int b = gid >> 6;
    int q = gid & 63;
    bool isPost = q >= 32;
    int j = q & 31;
    const float* x = x12 + (size_t)b * (2 * H_) + (isPost ? H_ : 0);
    const float* W = isPost ? post_W2 : prior_W2;
    const float* bb = isPost ? post_b2 : prior_b2;
    float m = bb[j], s = bb[S_ + j];
    for (int k = 0; k < H_; k++) {
        float xv = x[k];
        m = fmaf(xv, W[k * P2_ + j], m);
        s = fmaf(xv, W[k * P2_ + S_ + j], s);
    }
    s = softplus_f(s) + 0.1f;
    if (isPost) {
        out_posts_t[(size_t)b * P2_ + j] = m;
        out_posts_t[(size_t)b * P2_ + S_ + j] = s;
        float eps = noise_t[(size_t)b * S_ + j];
        float smp = fmaf(s, eps, m);
        state[(size_t)b * DS_ + D_ + j] = smp;
        out_states_t[(size_t)b * DS_ + D_ + j] = smp;
    } else {
        out_priors_t[(size_t)b * P2_ + j] = m;
        out_priors_t[(size_t)b * P2_ + S_ + j] = s;
    }
}

// ---------------- launch ----------------
extern "C" void kernel_launch(void* const* d_in, const int* in_sizes, int n_in,
                              void* d_out, int out_size) {
    const float* embed    = (const float*)d_in[0];
    const float* action   = (const float*)d_in[1];
    const float* noise    = (const float*)d_in[2];
    const float* in_state = (const float*)d_in[3];
    const float* za_W     = (const float*)d_in[4];
    const float* za_b     = (const float*)d_in[5];
    const float* gru_Wi   = (const float*)d_in[6];
    const float* gru_Wh   = (const float*)d_in[7];
    const float* gru_bi   = (const float*)d_in[8];
    const float* gru_bh   = (const float*)d_in[9];
    const float* prior_W1 = (const float*)d_in[10];
    const float* prior_b1 = (const float*)d_in[11];
    const float* prior_W2 = (const float*)d_in[12];
    const float* prior_b2 = (const float*)d_in[13];
    const float* post_W1  = (const float*)d_in[14];
    const float* post_b1  = (const float*)d_in[15];
    const float* post_W2  = (const float*)d_in[16];
    const float* post_b2  = (const float*)d_in[17];
    const void*  reset    = d_in[18];

    float* out = (float*)d_out;
    float* out_priors = out;
    float* out_posts  = out + (size_t)T_ * B_ * P2_;
    float* out_states = out + (size_t)2 * T_ * B_ * P2_;

    float *state, *za, *gi, *gh, *x12, *epost, *Wcat, *bcat;
    cudaGetSymbolAddress((void**)&state, g_state);
    cudaGetSymbolAddress((void**)&za,    g_za);
    cudaGetSymbolAddress((void**)&gi,    g_gi);
    cudaGetSymbolAddress((void**)&gh,    g_gh);
    cudaGetSymbolAddress((void**)&x12,   g_x12);
    cudaGetSymbolAddress((void**)&epost, g_epost);
    cudaGetSymbolAddress((void**)&Wcat,  g_Wcat);
    cudaGetSymbolAddress((void**)&bcat,  g_bcat);

    const int TPB = 256;

    detect_reset_kernel<<<1, 256>>>((const unsigned char*)reset);

    copy_state_kernel<<<(B_ * DS_ + TPB - 1) / TPB, TPB>>>(in_state, state);

    wcat_kernel<<<(D_ * 2 * H_ + TPB - 1) / TPB, TPB>>>(prior_W1, prior_b1, post_W1, post_b1, Wcat, bcat);

    // epost = embed @ post_W1[D:, :]  (all T at once, off critical path)
    gemm_f32<128, 128, 8, 8, 8><<<dim3(H_ / 128, (T_ * B_) / 128), 256>>>(
        T_ * B_, H_, E_,
        embed, E_,
        post_W1 + (size_t)D_ * H_, H_,
        epost, H_,
        nullptr, nullptr, 0, 0, 0);

    for (int t = 0; t < T_; t++) {
        reset_kernel<<<(B_ * DS_ + TPB - 1) / TPB, TPB>>>(reset, t, state);

        za_kernel<<<(B_ * H_ + TPB - 1) / TPB, TPB>>>(
            state, action + (size_t)t * B_ * A_, za_W, za_b, za);

        // gi = za @ gru_Wi + bi    [512, 6144], K=1024
        gemm_f32<128, 128, 8, 8, 8><<<dim3(G3_ / 128, B_ / 128), 256>>>(
            B_, G3_, H_, za, H_, gru_Wi, G3_, gi, G3_, gru_bi, nullptr, 0, 0, 0);

        // gh = h @ gru_Wh + bh     [512, 6144], K=2048
        gemm_f32<128, 128, 8, 8, 8><<<dim3(G3_ / 128, B_ / 128), 256>>>(
            B_, G3_, D_, state, DS_, gru_Wh, G3_, gh, G3_, gru_bh, nullptr, 0, 0, 0);

        gate_kernel<<<(B_ * D_ + TPB - 1) / TPB, TPB>>>(
            gi, gh, state, out_states + (size_t)t * B_ * DS_);

        // x12 = elu(h_new @ [prior_W1 | post_W1_top] + bcat (+ epost for cols>=1024))
        gemm_f32<64, 64, 16, 4, 4><<<dim3((2 * H_) / 64, B_ / 64), 256>>>(
            B_, 2 * H_, D_, state, DS_, Wcat, 2 * H_, x12, 2 * H_,
            bcat, epost + (size_t)t * B_ * H_, H_, H_, 1);

        heads_kernel<<<(B_ * 64 + TPB - 1) / TPB, TPB>>>(
            x12, prior_W2, prior_b2, post_W2, post_b2,
            noise + (size_t)t * B_ * S_, state,
            out_priors + (size_t)t * B_ * P2_,
            out_posts  + (size_t)t * B_ * P2_,
            out_states + (size_t)t * B_ * DS_);
    }
}

// round 6
// speedup vs baseline: 2.7380x; 2.7380x over previous
#include <cuda_runtime.h>
#include <cuda_bf16.h>
#include <math.h>
#include <stdint.h>

// ---------------- problem dims ----------------
#define T_  64
#define B_  512
#define E_  1536
#define A_  7
#define D_  2048
#define S_  32
#define H_  1024
#define DS_ 2080      // D + S
#define G3_ 6144      // 3*D
#define P2_ 64        // 2*S

// ---------------- device scratch (no allocs allowed) ----------------
__device__ __align__(16) float g_state[B_ * DS_];
__device__ __align__(16) float g_gi[B_ * G3_];
__device__ __align__(16) float g_gh[B_ * G3_];
__device__ __align__(16) float g_x12[B_ * 2 * H_];
__device__ __align__(16) float g_epost[(size_t)T_ * B_ * H_];   // 134 MB fp32
__device__ __align__(16) float g_bcat[2 * H_];
__device__ int g_reset_mode;   // 0 = bool(1B), 1 = int32, 2 = float32

// bf16 split buffers (hi/lo decomposition)
__device__ __align__(16) __nv_bfloat16 g_Wi_hi[H_ * G3_],  g_Wi_lo[H_ * G3_];     // [1024,6144]
__device__ __align__(16) __nv_bfloat16 g_Wh_hi[D_ * G3_],  g_Wh_lo[D_ * G3_];     // [2048,6144]
__device__ __align__(16) __nv_bfloat16 g_Wc_hi[D_ * 2 * H_], g_Wc_lo[D_ * 2 * H_];// [2048,2048]
__device__ __align__(16) __nv_bfloat16 g_We_hi[E_ * H_],   g_We_lo[E_ * H_];      // [1536,1024]
__device__ __align__(16) __nv_bfloat16 g_emb_hi[(size_t)T_ * B_ * E_], g_emb_lo[(size_t)T_ * B_ * E_];
__device__ __align__(16) __nv_bfloat16 g_za_hi[B_ * H_],   g_za_lo[B_ * H_];
__device__ __align__(16) __nv_bfloat16 g_h_hi[B_ * D_],    g_h_lo[B_ * D_];
__device__ __align__(16) __nv_bfloat16 g_xa_hi[B_ * D_],   g_xa_lo[B_ * D_];

// ---------------- helpers ----------------
__device__ __forceinline__ float elu_f(float x) { return x > 0.f ? x : expm1f(x); }
__device__ __forceinline__ float sigmoid_f(float x) { return 1.f / (1.f + expf(-x)); }
__device__ __forceinline__ float softplus_f(float x) {
    return fmaxf(x, 0.f) + log1pf(expf(-fabsf(x)));
}
__device__ __forceinline__ void split_bf16(float x, __nv_bfloat16& hi, __nv_bfloat16& lo) {
    __nv_bfloat16 h = __float2bfloat16(x);
    hi = h;
    lo = __float2bfloat16(x - __bfloat162float(h));
}

// ---------------- reset dtype sniffer ----------------
__global__ void detect_reset_kernel(const unsigned char* __restrict__ rbytes) {
    __shared__ int sawOdd, sawF32;
    if (threadIdx.x == 0) { sawOdd = 0; sawF32 = 0; }
    __syncthreads();
    for (int i = threadIdx.x; i < T_ * B_; i += blockDim.x) {
        unsigned char v = rbytes[i];
        if ((i & 3) == 3 && v == 0x3F) sawF32 = 1;
        if ((i & 3) != 0 && v != 0)    sawOdd = 1;
    }
    __syncthreads();
    if (threadIdx.x == 0) g_reset_mode = sawF32 ? 2 : (sawOdd ? 0 : 1);
}

__device__ __forceinline__ bool read_reset(const void* rp, int idx) {
    int mode = g_reset_mode;
    if (mode == 0) return ((const unsigned char*)rp)[idx] != 0;
    if (mode == 1) return ((const int*)rp)[idx] != 0;
    return ((const float*)rp)[idx] != 0.f;
}

// ---------------- tensor-core primitives ----------------
__device__ __forceinline__ uint32_t smem_u32(const void* p) {
    return (uint32_t)__cvta_generic_to_shared(p);
}
__device__ __forceinline__ void cp16(void* dst, const void* src) {
    asm volatile("cp.async.cg.shared.global [%0], [%1], 16;"
                 :: "r"(smem_u32(dst)), "l"(src));
}
__device__ __forceinline__ void cp_commit() { asm volatile("cp.async.commit_group;"); }
template<int N> __device__ __forceinline__ void cp_wait() {
    asm volatile("cp.async.wait_group %0;" :: "n"(N));
}
__device__ __forceinline__ void ldsm_x4(uint32_t r[4], const void* p) {
    uint32_t a = smem_u32(p);
    asm volatile("ldmatrix.sync.aligned.m8n8.x4.shared.b16 {%0,%1,%2,%3}, [%4];"
                 : "=r"(r[0]), "=r"(r[1]), "=r"(r[2]), "=r"(r[3]) : "r"(a));
}
__device__ __forceinline__ void ldsm_x4t(uint32_t r[4], const void* p) {
    uint32_t a = smem_u32(p);
    asm volatile("ldmatrix.sync.aligned.m8n8.x4.trans.shared.b16 {%0,%1,%2,%3}, [%4];"
                 : "=r"(r[0]), "=r"(r[1]), "=r"(r[2]), "=r"(r[3]) : "r"(a));
}
__device__ __forceinline__ void mma_bf16(float c[4], const uint32_t a[4], uint32_t b0, uint32_t b1) {
    asm volatile("mma.sync.aligned.m16n8k16.row.col.f32.bf16.bf16.f32 "
                 "{%0,%1,%2,%3}, {%4,%5,%6,%7}, {%8,%9}, {%0,%1,%2,%3};"
                 : "+f"(c[0]), "+f"(c[1]), "+f"(c[2]), "+f"(c[3])
                 : "r"(a[0]), "r"(a[1]), "r"(a[2]), "r"(a[3]), "r"(b0), "r"(b1));
}

// ---------------- bf16 3-term split GEMM ----------------
// C[M,N] = Ahi@Bhi + Ahi@Blo + Alo@Bhi  (fp32 accum)  + bias + add(cols>=addStart) + elu
// BM=64, BN=128, BK=32.  Requires M%64==0, N%128==0, K%32==0.
#define GBM 64
#define GBN 128
#define GBK 32
#define APITCH 40
#define BPITCH 136
#define GEMM_SMEM ((2*2*GBM*APITCH + 2*2*GBK*BPITCH) * 2)

__global__ void __launch_bounds__(256) gemm_bf16_3x(
    int M, int N, int K,
    const __nv_bfloat16* __restrict__ Ahi, const __nv_bfloat16* __restrict__ Alo, int lda,
    const __nv_bfloat16* __restrict__ Bhi, const __nv_bfloat16* __restrict__ Blo, int ldb,
    float* __restrict__ C, int ldc,
    const float* __restrict__ bias,
    const float* __restrict__ add, int addStart, int addLd, int doElu)
{
    extern __shared__ __align__(16) __nv_bfloat16 sm[];
    __nv_bfloat16* As = sm;                        // [2 stage][2 buf][GBM][APITCH]
    __nv_bfloat16* Bs = sm + 2 * 2 * GBM * APITCH; // [2 stage][2 buf][GBK][BPITCH]

    const int tid = threadIdx.x;
    const int m0 = blockIdx.y * GBM;
    const int n0 = blockIdx.x * GBN;
    const int wid = tid >> 5, lane = tid & 31;
    const int wm = (wid & 1) * 32;
    const int wn = (wid >> 1) * 32;

    float acc[2][4][4];
#pragma unroll
    for (int i = 0; i < 2; i++)
#pragma unroll
        for (int j = 0; j < 4; j++)
#pragma unroll
            for (int k = 0; k < 4; k++) acc[i][j][k] = 0.f;

    const int arow = tid >> 2, ach = (tid & 3) * 8;   // A: 256 chunks of 16B
    const int brow = tid >> 4, bch = (tid & 15) * 8;  // B: 512 chunks (2 per thread)

    auto load_stage = [&](int stage, int k0) {
        const __nv_bfloat16* asrc[2] = {Ahi, Alo};
        const __nv_bfloat16* bsrc[2] = {Bhi, Blo};
#pragma unroll
        for (int buf = 0; buf < 2; buf++) {
            cp16(&As[((stage * 2 + buf) * GBM + arow) * APITCH + ach],
                 asrc[buf] + (size_t)(m0 + arow) * lda + k0 + ach);
            cp16(&Bs[((stage * 2 + buf) * GBK + brow) * BPITCH + bch],
                 bsrc[buf] + (size_t)(k0 + brow) * ldb + n0 + bch);
            cp16(&Bs[((stage * 2 + buf) * GBK + brow + 16) * BPITCH + bch],
                 bsrc[buf] + (size_t)(k0 + brow + 16) * ldb + n0 + bch);
        }
    };

    const int KT = K / GBK;
    load_stage(0, 0);
    cp_commit();

    for (int kt = 0; kt < KT; kt++) {
        const int st = kt & 1;
        if (kt + 1 < KT) { load_stage((kt + 1) & 1, (kt + 1) * GBK); cp_commit(); cp_wait<1>(); }
        else cp_wait<0>();
        __syncthreads();

#pragma unroll
        for (int ks = 0; ks < GBK; ks += 16) {
            uint32_t ah[2][4], al[2][4], bh[2][4], bl[2][4];
#pragma unroll
            for (int mt = 0; mt < 2; mt++) {
                int row = wm + mt * 16 + (lane & 15);
                int col = ks + 8 * (lane >> 4);
                ldsm_x4(ah[mt], &As[((st * 2 + 0) * GBM + row) * APITCH + col]);
                ldsm_x4(al[mt], &As[((st * 2 + 1) * GBM + row) * APITCH + col]);
            }
#pragma unroll
            for (int j = 0; j < 2; j++) {
                int row = ks + (lane & 7) + 8 * ((lane >> 3) & 1);
                int col = wn + j * 16 + 8 * (lane >> 4);
                ldsm_x4t(bh[j], &Bs[((st * 2 + 0) * GBK + row) * BPITCH + col]);
                ldsm_x4t(bl[j], &Bs[((st * 2 + 1) * GBK + row) * BPITCH + col]);
            }
#pragma unroll
            for (int mt = 0; mt < 2; mt++)
#pragma unroll
                for (int nt = 0; nt < 4; nt++) {
                    uint32_t B0h = bh[nt >> 1][(nt & 1) * 2], B1h = bh[nt >> 1][(nt & 1) * 2 + 1];
                    uint32_t B0l = bl[nt >> 1][(nt & 1) * 2], B1l = bl[nt >> 1][(nt & 1) * 2 + 1];
                    mma_bf16(acc[mt][nt], ah[mt], B0h, B1h);
                    mma_bf16(acc[mt][nt], ah[mt], B0l, B1l);
                    mma_bf16(acc[mt][nt], al[mt], B0h, B1h);
                }
        }
        __syncthreads();
    }

    // epilogue
    const int g = lane >> 2, t2 = (lane & 3) * 2;
#pragma unroll
    for (int mt = 0; mt < 2; mt++)
#pragma unroll
        for (int nt = 0; nt < 4; nt++) {
            int col = n0 + wn + nt * 8 + t2;
#pragma unroll
            for (int half = 0; half < 2; half++) {
                int row = m0 + wm + mt * 16 + g + half * 8;
                float v0 = acc[mt][nt][half * 2 + 0];
                float v1 = acc[mt][nt][half * 2 + 1];
                if (bias) { v0 += bias[col]; v1 += bias[col + 1]; }
                if (add) {
                    if (col     >= addStart) v0 += add[(size_t)row * addLd + (col     - addStart)];
                    if (col + 1 >= addStart) v1 += add[(size_t)row * addLd + (col + 1 - addStart)];
                }
                if (doElu) { v0 = elu_f(v0); v1 = elu_f(v1); }
                C[(size_t)row * ldc + col]     = v0;
                C[(size_t)row * ldc + col + 1] = v1;
            }
        }
}

// ---------------- small kernels ----------------
__global__ void copy_state_kernel(const float* __restrict__ in_state, float* __restrict__ state) {
    int idx = blockIdx.x * blockDim.x + threadIdx.x;
    if (idx < B_ * DS_) state[idx] = in_state[idx];
}

__global__ void split_kernel(const float* __restrict__ src,
                             __nv_bfloat16* __restrict__ hi, __nv_bfloat16* __restrict__ lo,
                             size_t n) {
    size_t idx = (size_t)blockIdx.x * blockDim.x + threadIdx.x;
    if (idx >= n) return;
    split_bf16(src[idx], hi[idx], lo[idx]);
}

__global__ void wcat_split_kernel(const float* __restrict__ pW1, const float* __restrict__ pb1,
                                  const float* __restrict__ qW1, const float* __restrict__ qb1,
                                  __nv_bfloat16* __restrict__ hi, __nv_bfloat16* __restrict__ lo,
                                  float* __restrict__ bcat) {
    int idx = blockIdx.x * blockDim.x + threadIdx.x;
    if (idx < D_ * 2 * H_) {
        int k = idx / (2 * H_);
        int j = idx % (2 * H_);
        float v = (j < H_) ? pW1[k * H_ + j] : qW1[k * H_ + (j - H_)];
        split_bf16(v, hi[idx], lo[idx]);
    }
    if (idx < 2 * H_) bcat[idx] = (idx < H_) ? pb1[idx] : qb1[idx - H_];
}

// Fused: apply reset to state h-part (+ split h to bf16), compute za (+ split).
__global__ void reset_za_kernel(const void* __restrict__ reset_base, int t,
                                float* __restrict__ state,
                                const float* __restrict__ action_t,
                                const float* __restrict__ za_W, const float* __restrict__ za_b,
                                __nv_bfloat16* __restrict__ h_hi, __nv_bfloat16* __restrict__ h_lo,
                                __nv_bfloat16* __restrict__ za_hi, __nv_bfloat16* __restrict__ za_lo) {
    int idx = blockIdx.x * blockDim.x + threadIdx.x;
    if (idx < B_ * D_) {
        int b = idx / D_;
        bool r = read_reset(reset_base, t * B_ + b);
        float h = r ? 0.f : state[(size_t)b * DS_ + (idx % D_)];
        state[(size_t)b * DS_ + (idx % D_)] = h;
        split_bf16(h, h_hi[idx], h_lo[idx]);
    } else if (idx < B_ * D_ + B_ * H_) {
        int j2 = idx - B_ * D_;
        int b = j2 / H_;
        int j = j2 % H_;
        bool r = read_reset(reset_base, t * B_ + b);
        float acc = za_b[j];
        if (!r) {
            const float* z = state + (size_t)b * DS_ + D_;
#pragma unroll
            for (int k = 0; k < S_; k++) acc = fmaf(z[k], za_W[k * H_ + j], acc);
        }
        const float* a = action_t + (size_t)b * A_;
#pragma unroll
        for (int k = 0; k < A_; k++) acc = fmaf(a[k], za_W[(S_ + k) * H_ + j], acc);
        float za = elu_f(acc);
        split_bf16(za, za_hi[j2], za_lo[j2]);
    }
}

// GRU gate combine (adds biases), writes h_new to state + out + bf16 split for x12 GEMM
__global__ void gate_kernel(const float* __restrict__ gi, const float* __restrict__ gh,
                            const float* __restrict__ bi, const float* __restrict__ bh,
                            float* __restrict__ state, float* __restrict__ out_states_t,
                            __nv_bfloat16* __restrict__ xa_hi, __nv_bfloat16* __restrict__ xa_lo) {
    int idx = blockIdx.x * blockDim.x + threadIdx.x;
    if (idx >= B_ * D_) return;
    int b = idx / D_;
    int i = idx % D_;
    const float* gib = gi + (size_t)b * G3_;
    const float* ghb = gh + (size_t)b * G3_;
    float ir = gib[i] + bi[i],            hr = ghb[i] + bh[i];
    float iz = gib[D_ + i] + bi[D_ + i],  hz = ghb[D_ + i] + bh[D_ + i];
    float inn = gib[2 * D_ + i] + bi[2 * D_ + i], hn = ghb[2 * D_ + i] + bh[2 * D_ + i];
    float h = state[(size_t)b * DS_ + i];
    float rg = sigmoid_f(ir + hr);
    float zg = sigmoid_f(iz + hz);
    float n = tanhf(inn + rg * hn);
    float hnew = (1.f - zg) * n + zg * h;
    state[(size_t)b * DS_ + i] = hnew;
    out_states_t[(size_t)b * DS_ + i] = hnew;
    split_bf16(hnew, xa_hi[idx], xa_lo[idx]);
}

// Heads: prior/post W2 matmuls + mean/std + sample
__global__ void heads_kernel(const float* __restrict__ x12,
                             const float* __restrict__ prior_W2, const float* __restrict__ prior_b2,
                             const float* __restrict__ post_W2, const float* __restrict__ post_b2,
                             const float* __restrict__ noise_t,
                             float* __restrict__ state,
                             float* __restrict__ out_priors_t, float* __restrict__ out_posts_t,
                             float* __restrict__ out_states_t) {
    int gid = blockIdx.x * blockDim.x + threadIdx.x;
    if (gid >= B_ * 64) return;
    int b = gid >> 6;
    int q = gid & 63;
    bool isPost = q >= 32;
    int j = q & 31;
    const float* x = x12 + (size_t)b * (2 * H_) + (isPost ? H_ : 0);
    const float* W = isPost ? post_W2 : prior_W2;
    const float* bb = isPost ? post_b2 : prior_b2;
    float m = bb[j], s = bb[S_ + j];
    for (int k = 0; k < H_; k++) {
        float xv = x[k];
        m = fmaf(xv, W[k * P2_ + j], m);
        s = fmaf(xv, W[k * P2_ + S_ + j], s);
    }
    s = softplus_f(s) + 0.1f;
    if (isPost) {
        out_posts_t[(size_t)b * P2_ + j] = m;
        out_posts_t[(size_t)b * P2_ + S_ + j] = s;
        float eps = noise_t[(size_t)b * S_ + j];
        float smp = fmaf(s, eps, m);
        state[(size_t)b * DS_ + D_ + j] = smp;
        out_states_t[(size_t)b * DS_ + D_ + j] = smp;
    } else {
        out_priors_t[(size_t)b * P2_ + j] = m;
        out_priors_t[(size_t)b * P2_ + S_ + j] = s;
    }
}

// ---------------- launch ----------------
extern "C" void kernel_launch(void* const* d_in, const int* in_sizes, int n_in,
                              void* d_out, int out_size) {
    const float* embed    = (const float*)d_in[0];
    const float* action   = (const float*)d_in[1];
    const float* noise    = (const float*)d_in[2];
    const float* in_state = (const float*)d_in[3];
    const float* za_W     = (const float*)d_in[4];
    const float* za_b     = (const float*)d_in[5];
    const float* gru_Wi   = (const float*)d_in[6];
    const float* gru_Wh   = (const float*)d_in[7];
    const float* gru_bi   = (const float*)d_in[8];
    const float* gru_bh   = (const float*)d_in[9];
    const float* prior_W1 = (const float*)d_in[10];
    const float* prior_b1 = (const float*)d_in[11];
    const float* prior_W2 = (const float*)d_in[12];
    const float* prior_b2 = (const float*)d_in[13];
    const float* post_W1  = (const float*)d_in[14];
    const float* post_b1  = (const float*)d_in[15];
    const float* post_W2  = (const float*)d_in[16];
    const float* post_b2  = (const float*)d_in[17];
    const void*  reset    = d_in[18];

    float* out = (float*)d_out;
    float* out_priors = out;
    float* out_posts  = out + (size_t)T_ * B_ * P2_;
    float* out_states = out + (size_t)2 * T_ * B_ * P2_;

    float *state, *gi, *gh, *x12, *epost, *bcat;
    __nv_bfloat16 *Wi_hi, *Wi_lo, *Wh_hi, *Wh_lo, *Wc_hi, *Wc_lo, *We_hi, *We_lo;
    __nv_bfloat16 *emb_hi, *emb_lo, *za_hi, *za_lo, *h_hi, *h_lo, *xa_hi, *xa_lo;
    cudaGetSymbolAddress((void**)&state, g_state);
    cudaGetSymbolAddress((void**)&gi,    g_gi);
    cudaGetSymbolAddress((void**)&gh,    g_gh);
    cudaGetSymbolAddress((void**)&x12,   g_x12);
    cudaGetSymbolAddress((void**)&epost, g_epost);
    cudaGetSymbolAddress((void**)&bcat,  g_bcat);
    cudaGetSymbolAddress((void**)&Wi_hi, g_Wi_hi); cudaGetSymbolAddress((void**)&Wi_lo, g_Wi_lo);
    cudaGetSymbolAddress((void**)&Wh_hi, g_Wh_hi); cudaGetSymbolAddress((void**)&Wh_lo, g_Wh_lo);
    cudaGetSymbolAddress((void**)&Wc_hi, g_Wc_hi); cudaGetSymbolAddress((void**)&Wc_lo, g_Wc_lo);
    cudaGetSymbolAddress((void**)&We_hi, g_We_hi); cudaGetSymbolAddress((void**)&We_lo, g_We_lo);
    cudaGetSymbolAddress((void**)&emb_hi, g_emb_hi); cudaGetSymbolAddress((void**)&emb_lo, g_emb_lo);
    cudaGetSymbolAddress((void**)&za_hi, g_za_hi); cudaGetSymbolAddress((void**)&za_lo, g_za_lo);
    cudaGetSymbolAddress((void**)&h_hi,  g_h_hi);  cudaGetSymbolAddress((void**)&h_lo,  g_h_lo);
    cudaGetSymbolAddress((void**)&xa_hi, g_xa_hi); cudaGetSymbolAddress((void**)&xa_lo, g_xa_lo);

    cudaFuncSetAttribute(gemm_bf16_3x, cudaFuncAttributeMaxDynamicSharedMemorySize, GEMM_SMEM);

    const int TPB = 256;

    detect_reset_kernel<<<1, 256>>>((const unsigned char*)reset);
    copy_state_kernel<<<(B_ * DS_ + TPB - 1) / TPB, TPB>>>(in_state, state);

    // weight splits (once per call, off critical path)
    {
        size_t n;
        n = (size_t)H_ * G3_;
        split_kernel<<<(unsigned)((n + TPB - 1) / TPB), TPB>>>(gru_Wi, Wi_hi, Wi_lo, n);
        n = (size_t)D_ * G3_;
        split_kernel<<<(unsigned)((n + TPB - 1) / TPB), TPB>>>(gru_Wh, Wh_hi, Wh_lo, n);
        n = (size_t)E_ * H_;
        split_kernel<<<(unsigned)((n + TPB - 1) / TPB), TPB>>>(post_W1 + (size_t)D_ * H_, We_hi, We_lo, n);
        n = (size_t)T_ * B_ * E_;
        split_kernel<<<(unsigned)((n + TPB - 1) / TPB), TPB>>>(embed, emb_hi, emb_lo, n);
        wcat_split_kernel<<<(D_ * 2 * H_ + TPB - 1) / TPB, TPB>>>(
            prior_W1, prior_b1, post_W1, post_b1, Wc_hi, Wc_lo, bcat);
    }

    // epost = embed @ post_W1[D:, :]   (M=T*B=32768, N=1024, K=1536)
    gemm_bf16_3x<<<dim3(H_ / GBN, (T_ * B_) / GBM), 256, GEMM_SMEM>>>(
        T_ * B_, H_, E_, emb_hi, emb_lo, E_, We_hi, We_lo, H_,
        epost, H_, nullptr, nullptr, 0, 0, 0);

    for (int t = 0; t < T_; t++) {
        reset_za_kernel<<<(B_ * (D_ + H_) + TPB - 1) / TPB, TPB>>>(
            reset, t, state, action + (size_t)t * B_ * A_, za_W, za_b,
            h_hi, h_lo, za_hi, za_lo);

        // gi = za @ gru_Wi    (M=512, N=6144, K=1024)
        gemm_bf16_3x<<<dim3(G3_ / GBN, B_ / GBM), 256, GEMM_SMEM>>>(
            B_, G3_, H_, za_hi, za_lo, H_, Wi_hi, Wi_lo, G3_,
            gi, G3_, nullptr, nullptr, 0, 0, 0);

        // gh = h @ gru_Wh     (M=512, N=6144, K=2048)
        gemm_bf16_3x<<<dim3(G3_ / GBN, B_ / GBM), 256, GEMM_SMEM>>>(
            B_, G3_, D_, h_hi, h_lo, D_, Wh_hi, Wh_lo, G3_,
            gh, G3_, nullptr, nullptr, 0, 0, 0);

        gate_kernel<<<(B_ * D_ + TPB - 1) / TPB, TPB>>>(
            gi, gh, gru_bi, gru_bh, state, out_states + (size_t)t * B_ * DS_,
            xa_hi, xa_lo);

        // x12 = elu(h_new @ Wcat + bcat + epost[cols>=1024])  (M=512, N=2048, K=2048)
        gemm_bf16_3x<<<dim3((2 * H_) / GBN, B_ / GBM), 256, GEMM_SMEM>>>(
            B_, 2 * H_, D_, xa_hi, xa_lo, D_, Wc_hi, Wc_lo, 2 * H_,
            x12, 2 * H_, bcat, epost + (size_t)t * B_ * H_, H_, H_, 1);

        heads_kernel<<<(B_ * 64 + TPB - 1) / TPB, TPB>>>(
            x12, prior_W2, prior_b2, post_W2, post_b2,
            noise + (size_t)t * B_ * S_, state,
            out_priors + (size_t)t * B_ * P2_,
            out_posts  + (size_t)t * B_ * P2_,
            out_states + (size_t)t * B_ * DS_);
    }
}

// round 7
// speedup vs baseline: 4.9275x; 1.7997x over previous
#include <cuda_runtime.h>
#include <cuda_fp16.h>
#include <math.h>
#include <stdint.h>

// ---------------- problem dims ----------------
#define T_  64
#define B_  512
#define E_  1536
#define A_  7
#define D_  2048
#define S_  32
#define H_  1024
#define DS_ 2080      // D + S
#define G3_ 6144      // 3*D
#define P2_ 64        // 2*S

// ---------------- device scratch (no allocs allowed) ----------------
__device__ __align__(16) float g_state[B_ * DS_];
__device__ __align__(16) float g_gi[B_ * G3_];
__device__ __align__(16) float g_gh[B_ * G3_];
__device__ __align__(16) float g_x12[B_ * 2 * H_];
__device__ __align__(16) float g_epost[(size_t)T_ * B_ * H_];   // 134 MB fp32
__device__ __align__(16) float g_bcat[2 * H_];
__device__ int g_reset_mode;   // 0 = bool(1B), 1 = int32, 2 = float32

// fp16 operand buffers
__device__ __align__(16) __half g_Wi_h[H_ * G3_];       // [1024,6144]
__device__ __align__(16) __half g_Wh_h[D_ * G3_];       // [2048,6144]
__device__ __align__(16) __half g_Wc_h[D_ * 2 * H_];    // [2048,2048]
__device__ __align__(16) __half g_We_h[E_ * H_];        // [1536,1024]
__device__ __align__(16) __half g_emb_h[(size_t)T_ * B_ * E_];
__device__ __align__(16) __half g_za_h[B_ * H_];
__device__ __align__(16) __half g_h_h[B_ * D_];
__device__ __align__(16) __half g_xa_h[B_ * D_];

// ---------------- helpers ----------------
__device__ __forceinline__ float elu_f(float x) { return x > 0.f ? x : expm1f(x); }
__device__ __forceinline__ float sigmoid_f(float x) { return 1.f / (1.f + expf(-x)); }
__device__ __forceinline__ float softplus_f(float x) {
    return fmaxf(x, 0.f) + log1pf(expf(-fabsf(x)));
}

// ---------------- reset dtype sniffer ----------------
__global__ void detect_reset_kernel(const unsigned char* __restrict__ rbytes) {
    __shared__ int sawOdd, sawF32;
    if (threadIdx.x == 0) { sawOdd = 0; sawF32 = 0; }
    __syncthreads();
    for (int i = threadIdx.x; i < T_ * B_; i += blockDim.x) {
        unsigned char v = rbytes[i];
        if ((i & 3) == 3 && v == 0x3F) sawF32 = 1;
        if ((i & 3) != 0 && v != 0)    sawOdd = 1;
    }
    __syncthreads();
    if (threadIdx.x == 0) g_reset_mode = sawF32 ? 2 : (sawOdd ? 0 : 1);
}

__device__ __forceinline__ bool read_reset(const void* rp, int idx) {
    int mode = g_reset_mode;
    if (mode == 0) return ((const unsigned char*)rp)[idx] != 0;
    if (mode == 1) return ((const int*)rp)[idx] != 0;
    return ((const float*)rp)[idx] != 0.f;
}

// ---------------- tensor-core primitives ----------------
__device__ __forceinline__ uint32_t smem_u32(const void* p) {
    return (uint32_t)__cvta_generic_to_shared(p);
}
__device__ __forceinline__ void cp16(void* dst, const void* src) {
    asm volatile("cp.async.cg.shared.global [%0], [%1], 16;"
                 :: "r"(smem_u32(dst)), "l"(src));
}
__device__ __forceinline__ void cp_commit() { asm volatile("cp.async.commit_group;"); }
template<int N> __device__ __forceinline__ void cp_wait() {
    asm volatile("cp.async.wait_group %0;" :: "n"(N));
}
__device__ __forceinline__ void ldsm_x4(uint32_t r[4], const void* p) {
    uint32_t a = smem_u32(p);
    asm volatile("ldmatrix.sync.aligned.m8n8.x4.shared.b16 {%0,%1,%2,%3}, [%4];"
                 : "=r"(r[0]), "=r"(r[1]), "=r"(r[2]), "=r"(r[3]) : "r"(a));
}
__device__ __forceinline__ void ldsm_x4t(uint32_t r[4], const void* p) {
    uint32_t a = smem_u32(p);
    asm volatile("ldmatrix.sync.aligned.m8n8.x4.trans.shared.b16 {%0,%1,%2,%3}, [%4];"
                 : "=r"(r[0]), "=r"(r[1]), "=r"(r[2]), "=r"(r[3]) : "r"(a));
}
__device__ __forceinline__ void mma_f16(float c[4], const uint32_t a[4], uint32_t b0, uint32_t b1) {
    asm volatile("mma.sync.aligned.m16n8k16.row.col.f32.f16.f16.f32 "
                 "{%0,%1,%2,%3}, {%4,%5,%6,%7}, {%8,%9}, {%0,%1,%2,%3};"
                 : "+f"(c[0]), "+f"(c[1]), "+f"(c[2]), "+f"(c[3])
                 : "r"(a[0]), "r"(a[1]), "r"(a[2]), "r"(a[3]), "r"(b0), "r"(b1));
}

// ---------------- fp16 single-pass GEMM ----------------
// C[M,N] = A[M,K] @ B[K,N] (+bias)(+add for cols>=addStart)(elu)
// lda = K, ldb = ldc = N. BM=64, BN=128, BK=32. grid (N/128, M/64, z).
// If gridDim.z == 2 and blockIdx.z == 1, uses the second descriptor (A2,B2,C2,K2).
#define GBM 64
#define GBN 128
#define GBK 32
#define APITCH 40
#define BPITCH 136

__global__ void __launch_bounds__(256) gemm16(
    const __half* __restrict__ A, const __half* __restrict__ Bm,
    float* __restrict__ C, int K, int N,
    const __half* __restrict__ A2, const __half* __restrict__ B2,
    float* __restrict__ C2, int K2,
    const float* __restrict__ bias,
    const float* __restrict__ add, int addStart, int addLd, int doElu)
{
    if (blockIdx.z == 1) { A = A2; Bm = B2; C = C2; K = K2; }

    __shared__ __align__(16) __half As[2][GBM][APITCH];
    __shared__ __align__(16) __half Bs[2][GBK][BPITCH];

    const int tid = threadIdx.x;
    const int m0 = blockIdx.y * GBM;
    const int n0 = blockIdx.x * GBN;
    const int wid = tid >> 5, lane = tid & 31;
    const int wm = (wid & 1) * 32;
    const int wn = (wid >> 1) * 32;

    float acc[2][4][4];
#pragma unroll
    for (int i = 0; i < 2; i++)
#pragma unroll
        for (int j = 0; j < 4; j++)
#pragma unroll
            for (int k = 0; k < 4; k++) acc[i][j][k] = 0.f;

    const int arow = tid >> 2, ach = (tid & 3) * 8;
    const int brow = tid >> 4, bch = (tid & 15) * 8;

    auto load_stage = [&](int st, int k0) {
        cp16(&As[st][arow][ach], A + (size_t)(m0 + arow) * K + k0 + ach);
        cp16(&Bs[st][brow][bch], Bm + (size_t)(k0 + brow) * N + n0 + bch);
        cp16(&Bs[st][brow + 16][bch], Bm + (size_t)(k0 + brow + 16) * N + n0 + bch);
    };

    const int KT = K / GBK;
    load_stage(0, 0);
    cp_commit();

    for (int kt = 0; kt < KT; kt++) {
        const int st = kt & 1;
        if (kt + 1 < KT) { load_stage((kt + 1) & 1, (kt + 1) * GBK); cp_commit(); cp_wait<1>(); }
        else cp_wait<0>();
        __syncthreads();

#pragma unroll
        for (int ks = 0; ks < GBK; ks += 16) {
            uint32_t a[2][4], bq[2][4];
#pragma unroll
            for (int mt = 0; mt < 2; mt++) {
                int row = wm + mt * 16 + (lane & 15);
                int col = ks + 8 * (lane >> 4);
                ldsm_x4(a[mt], &As[st][row][col]);
            }
#pragma unroll
            for (int j = 0; j < 2; j++) {
                int row = ks + (lane & 7) + 8 * ((lane >> 3) & 1);
                int col = wn + j * 16 + 8 * (lane >> 4);
                ldsm_x4t(bq[j], &Bs[st][row][col]);
            }
#pragma unroll
            for (int mt = 0; mt < 2; mt++)
#pragma unroll
                for (int nt = 0; nt < 4; nt++)
                    mma_f16(acc[mt][nt], a[mt],
                            bq[nt >> 1][(nt & 1) * 2], bq[nt >> 1][(nt & 1) * 2 + 1]);
        }
        __syncthreads();
    }

    const int g = lane >> 2, t2 = (lane & 3) * 2;
#pragma unroll
    for (int mt = 0; mt < 2; mt++)
#pragma unroll
        for (int nt = 0; nt < 4; nt++) {
            int col = n0 + wn + nt * 8 + t2;
#pragma unroll
            for (int half = 0; half < 2; half++) {
                int row = m0 + wm + mt * 16 + g + half * 8;
                float v0 = acc[mt][nt][half * 2 + 0];
                float v1 = acc[mt][nt][half * 2 + 1];
                if (bias) { v0 += bias[col]; v1 += bias[col + 1]; }
                if (add) {
                    if (col     >= addStart) v0 += add[(size_t)row * addLd + (col     - addStart)];
                    if (col + 1 >= addStart) v1 += add[(size_t)row * addLd + (col + 1 - addStart)];
                }
                if (doElu) { v0 = elu_f(v0); v1 = elu_f(v1); }
                C[(size_t)row * (size_t)N + col]     = v0;
                C[(size_t)row * (size_t)N + col + 1] = v1;
            }
        }
}

// ---------------- small kernels ----------------
__global__ void copy_state_kernel(const float* __restrict__ in_state, float* __restrict__ state) {
    int idx = blockIdx.x * blockDim.x + threadIdx.x;
    if (idx < B_ * DS_) state[idx] = in_state[idx];
}

__global__ void conv_kernel(const float* __restrict__ src, __half* __restrict__ dst, size_t n) {
    size_t idx = (size_t)blockIdx.x * blockDim.x + threadIdx.x;
    if (idx < n) dst[idx] = __float2half_rn(src[idx]);
}

__global__ void wcat_conv_kernel(const float* __restrict__ pW1, const float* __restrict__ pb1,
                                 const float* __restrict__ qW1, const float* __restrict__ qb1,
                                 __half* __restrict__ Wc, float* __restrict__ bcat) {
    int idx = blockIdx.x * blockDim.x + threadIdx.x;
    if (idx < D_ * 2 * H_) {
        int k = idx / (2 * H_);
        int j = idx % (2 * H_);
        float v = (j < H_) ? pW1[k * H_ + j] : qW1[k * H_ + (j - H_)];
        Wc[idx] = __float2half_rn(v);
    }
    if (idx < 2 * H_) bcat[idx] = (idx < H_) ? pb1[idx] : qb1[idx - H_];
}

// Fused: apply reset to state h-part (+ fp16 h), compute za (+ fp16).
__global__ void reset_za_kernel(const void* __restrict__ reset_base, int t,
                                float* __restrict__ state,
                                const float* __restrict__ action_t,
                                const float* __restrict__ za_W, const float* __restrict__ za_b,
                                __half* __restrict__ h_h, __half* __restrict__ za_h) {
    int idx = blockIdx.x * blockDim.x + threadIdx.x;
    if (idx < B_ * D_) {
        int b = idx / D_;
        bool r = read_reset(reset_base, t * B_ + b);
        float h = r ? 0.f : state[(size_t)b * DS_ + (idx % D_)];
        state[(size_t)b * DS_ + (idx % D_)] = h;
        h_h[idx] = __float2half_rn(h);
    } else if (idx < B_ * D_ + B_ * H_) {
        int j2 = idx - B_ * D_;
        int b = j2 / H_;
        int j = j2 % H_;
        bool r = read_reset(reset_base, t * B_ + b);
        float acc = za_b[j];
        if (!r) {
            const float* z = state + (size_t)b * DS_ + D_;
#pragma unroll
            for (int k = 0; k < S_; k++) acc = fmaf(z[k], za_W[k * H_ + j], acc);
        }
        const float* a = action_t + (size_t)b * A_;
#pragma unroll
        for (int k = 0; k < A_; k++) acc = fmaf(a[k], za_W[(S_ + k) * H_ + j], acc);
        za_h[j2] = __float2half_rn(elu_f(acc));
    }
}

// GRU gate combine (adds biases); writes h_new to state + out + fp16 for x12 GEMM.
__global__ void gate_kernel(const float* __restrict__ gi, const float* __restrict__ gh,
                            const float* __restrict__ bi, const float* __restrict__ bh,
                            float* __restrict__ state, float* __restrict__ out_states_t,
                            __half* __restrict__ xa_h) {
    int idx = blockIdx.x * blockDim.x + threadIdx.x;
    if (idx >= B_ * D_) return;
    int b = idx / D_;
    int i = idx % D_;
    const float* gib = gi + (size_t)b * G3_;
    const float* ghb = gh + (size_t)b * G3_;
    float ir = gib[i] + bi[i],            hr = ghb[i] + bh[i];
    float iz = gib[D_ + i] + bi[D_ + i],  hz = ghb[D_ + i] + bh[D_ + i];
    float inn = gib[2 * D_ + i] + bi[2 * D_ + i], hn = ghb[2 * D_ + i] + bh[2 * D_ + i];
    float h = state[(size_t)b * DS_ + i];
    float rg = sigmoid_f(ir + hr);
    float zg = sigmoid_f(iz + hz);
    float n = tanhf(inn + rg * hn);
    float hnew = (1.f - zg) * n + zg * h;
    state[(size_t)b * DS_ + i] = hnew;
    out_states_t[(size_t)b * DS_ + i] = hnew;
    xa_h[idx] = __float2half_rn(hnew);
}

// Heads: block per batch row; x12 row staged in smem; 128 threads = 128 outputs.
__global__ void __launch_bounds__(128) heads_kernel(
        const float* __restrict__ x12,
        const float* __restrict__ prior_W2, const float* __restrict__ prior_b2,
        const float* __restrict__ post_W2, const float* __restrict__ post_b2,
        const float* __restrict__ noise_t,
        float* __restrict__ state,
        float* __restrict__ out_priors_t, float* __restrict__ out_posts_t,
        float* __restrict__ out_states_t) {
    int b = blockIdx.x;
    __shared__ __align__(16) float xs[2 * H_];
    __shared__ float res[128];
    const float4* src = (const float4*)(x12 + (size_t)b * 2 * H_);
    float4* dst4 = (float4*)xs;
#pragma unroll
    for (int i = threadIdx.x; i < (2 * H_) / 4; i += 128) dst4[i] = src[i];
    __syncthreads();

    int head = threadIdx.x >> 6;        // 0 = prior, 1 = post
    int j = threadIdx.x & 63;
    const float* x = xs + head * H_;
    const float* W = head ? post_W2 : prior_W2;
    const float* bb = head ? post_b2 : prior_b2;
    float acc = bb[j];
#pragma unroll 8
    for (int k = 0; k < H_; k++) acc = fmaf(x[k], W[k * P2_ + j], acc);
    if (j >= S_) acc = softplus_f(acc) + 0.1f;
    res[threadIdx.x] = acc;
    __syncthreads();

    float* outp = head ? out_posts_t : out_priors_t;
    outp[(size_t)b * P2_ + j] = acc;
    if (head == 1 && j < S_) {
        float mean = res[64 + j];
        float std  = res[64 + S_ + j];
        float smp = fmaf(std, noise_t[(size_t)b * S_ + j], mean);
        state[(size_t)b * DS_ + D_ + j] = smp;
        out_states_t[(size_t)b * DS_ + D_ + j] = smp;
    }
}

// ---------------- launch ----------------
extern "C" void kernel_launch(void* const* d_in, const int* in_sizes, int n_in,
                              void* d_out, int out_size) {
    const float* embed    = (const float*)d_in[0];
    const float* action   = (const float*)d_in[1];
    const float* noise    = (const float*)d_in[2];
    const float* in_state = (const float*)d_in[3];
    const float* za_W     = (const float*)d_in[4];
    const float* za_b     = (const float*)d_in[5];
    const float* gru_Wi   = (const float*)d_in[6];
    const float* gru_Wh   = (const float*)d_in[7];
    const float* gru_bi   = (const float*)d_in[8];
    const float* gru_bh   = (const float*)d_in[9];
    const float* prior_W1 = (const float*)d_in[10];
    const float* prior_b1 = (const float*)d_in[11];
    const float* prior_W2 = (const float*)d_in[12];
    const float* prior_b2 = (const float*)d_in[13];
    const float* post_W1  = (const float*)d_in[14];
    const float* post_b1  = (const float*)d_in[15];
    const float* post_W2  = (const float*)d_in[16];
    const float* post_b2  = (const float*)d_in[17];
    const void*  reset    = d_in[18];

    float* out = (float*)d_out;
    float* out_priors = out;
    float* out_posts  = out + (size_t)T_ * B_ * P2_;
    float* out_states = out + (size_t)2 * T_ * B_ * P2_;

    float *state, *gi, *gh, *x12, *epost, *bcat;
    __half *Wi_h, *Wh_h, *Wc_h, *We_h, *emb_h, *za_h, *h_h, *xa_h;
    cudaGetSymbolAddress((void**)&state, g_state);
    cudaGetSymbolAddress((void**)&gi,    g_gi);
    cudaGetSymbolAddress((void**)&gh,    g_gh);
    cudaGetSymbolAddress((void**)&x12,   g_x12);
    cudaGetSymbolAddress((void**)&epost, g_epost);
    cudaGetSymbolAddress((void**)&bcat,  g_bcat);
    cudaGetSymbolAddress((void**)&Wi_h,  g_Wi_h);
    cudaGetSymbolAddress((void**)&Wh_h,  g_Wh_h);
    cudaGetSymbolAddress((void**)&Wc_h,  g_Wc_h);
    cudaGetSymbolAddress((void**)&We_h,  g_We_h);
    cudaGetSymbolAddress((void**)&emb_h, g_emb_h);
    cudaGetSymbolAddress((void**)&za_h,  g_za_h);
    cudaGetSymbolAddress((void**)&h_h,   g_h_h);
    cudaGetSymbolAddress((void**)&xa_h,  g_xa_h);

    const int TPB = 256;

    detect_reset_kernel<<<1, 256>>>((const unsigned char*)reset);
    copy_state_kernel<<<(B_ * DS_ + TPB - 1) / TPB, TPB>>>(in_state, state);

    // weight/embed conversions (once per call)
    {
        size_t n;
        n = (size_t)H_ * G3_;
        conv_kernel<<<(unsigned)((n + TPB - 1) / TPB), TPB>>>(gru_Wi, Wi_h, n);
        n = (size_t)D_ * G3_;
        conv_kernel<<<(unsigned)((n + TPB - 1) / TPB), TPB>>>(gru_Wh, Wh_h, n);
        n = (size_t)E_ * H_;
        conv_kernel<<<(unsigned)((n + TPB - 1) / TPB), TPB>>>(post_W1 + (size_t)D_ * H_, We_h, n);
        n = (size_t)T_ * B_ * E_;
        conv_kernel<<<(unsigned)((n + TPB - 1) / TPB), TPB>>>(embed, emb_h, n);
        wcat_conv_kernel<<<(D_ * 2 * H_ + TPB - 1) / TPB, TPB>>>(
            prior_W1, prior_b1, post_W1, post_b1, Wc_h, bcat);
    }

    // epost = embed @ post_W1[D:, :]   (M=32768, N=1024, K=1536)
    gemm16<<<dim3(H_ / GBN, (T_ * B_) / GBM, 1), 256>>>(
        emb_h, We_h, epost, E_, H_,
        nullptr, nullptr, nullptr, 0,
        nullptr, nullptr, 0, 0, 0);

    for (int t = 0; t < T_; t++) {
        reset_za_kernel<<<(B_ * (D_ + H_) + TPB - 1) / TPB, TPB>>>(
            reset, t, state, action + (size_t)t * B_ * A_, za_W, za_b, h_h, za_h);

        // fused launch: z=0 -> gi = za @ Wi (K=1024); z=1 -> gh = h @ Wh (K=2048)
        gemm16<<<dim3(G3_ / GBN, B_ / GBM, 2), 256>>>(
            za_h, Wi_h, gi, H_, G3_,
            h_h, Wh_h, gh, D_,
            nullptr, nullptr, 0, 0, 0);

        gate_kernel<<<(B_ * D_ + TPB - 1) / TPB, TPB>>>(
            gi, gh, gru_bi, gru_bh, state, out_states + (size_t)t * B_ * DS_, xa_h);

        // x12 = elu(h_new @ Wcat + bcat + epost[cols>=1024])  (M=512, N=2048, K=2048)
        gemm16<<<dim3((2 * H_) / GBN, B_ / GBM, 1), 256>>>(
            xa_h, Wc_h, x12, D_, 2 * H_,
            nullptr, nullptr, nullptr, 0,
            bcat, epost + (size_t)t * B_ * H_, H_, H_, 1);

        heads_kernel<<<B_, 128>>>(
            x12, prior_W2, prior_b2, post_W2, post_b2,
            noise + (size_t)t * B_ * S_, state,
            out_priors + (size_t)t * B_ * P2_,
            out_posts  + (size_t)t * B_ * P2_,
            out_states + (size_t)t * B_ * DS_);
    }
}